// round 1
// baseline (speedup 1.0000x reference)
#include <cuda_runtime.h>
#include <math.h>

#define NEG_SLOPE 0.1f
#define RES_SCALE 0.70710678118654752440f
#define DEMOD_EPS 1e-5f

// ---------------------------------------------------------------------------
// Scratch (static device globals; allocation inside kernel_launch is banned)
// ---------------------------------------------------------------------------
__device__ float g_y1[8 * 256 * 64 * 64];   // block1 output, 33.5 MB
__device__ float g_wT1[256 * 9 * 256];      // conv1 weights transposed [ci][k][oc]
__device__ float g_wT2[256 * 9 * 128];      // conv2 weights transposed
__device__ float g_s1[8 * 256];
__device__ float g_n1[8 * 256];
__device__ float g_s2[8 * 256];
__device__ float g_n2[8 * 128];
__device__ float g_d1[8 * 256];
__device__ float g_d2[8 * 128];

// ---------------------------------------------------------------------------
// Bilinear 2x upsample sample (half-pixel, matches jax.image.resize 'bilinear'
// including edge renormalization).  (yy,xx) are coords in the 2x grid.
// out[2k]   = 0.25*in[k-1] + 0.75*in[k]   (clamped)
// out[2k+1] = 0.75*in[k]   + 0.25*in[k+1] (clamped)
// ---------------------------------------------------------------------------
__device__ __forceinline__ float bilin_up(const float* __restrict__ plane,
                                          int yy, int xx, int Hin, int Win) {
    int ky = yy >> 1, kx = xx >> 1;
    int ylo, yhi, xlo, xhi;
    float wy, wx;  // weight of (ylo, xlo)
    if (yy & 1) { ylo = ky; yhi = (ky + 1 < Hin) ? ky + 1 : Hin - 1; wy = 0.75f; }
    else        { ylo = (ky - 1 > 0) ? ky - 1 : 0; yhi = ky;         wy = 0.25f; }
    if (xx & 1) { xlo = kx; xhi = (kx + 1 < Win) ? kx + 1 : Win - 1; wx = 0.75f; }
    else        { xlo = (kx - 1 > 0) ? kx - 1 : 0; xhi = kx;         wx = 0.25f; }
    float v00 = plane[ylo * Win + xlo];
    float v01 = plane[ylo * Win + xhi];
    float v10 = plane[yhi * Win + xlo];
    float v11 = plane[yhi * Win + xhi];
    float top = wx * v00 + (1.f - wx) * v01;
    float bot = wx * v10 + (1.f - wx) * v11;
    return wy * top + (1.f - wy) * bot;
}

// ---------------------------------------------------------------------------
// Affine: out[b,o] = dot(vec[b,:512], W[o,:512]) + bias[o]; one warp per (b,o)
// ---------------------------------------------------------------------------
__global__ void __launch_bounds__(256) affine_kernel(
    const float* __restrict__ vec, const float* __restrict__ Wm,
    const float* __restrict__ bias, float* __restrict__ out, int OUT) {
    int gw = (blockIdx.x * blockDim.x + threadIdx.x) >> 5;
    int lane = threadIdx.x & 31;
    if (gw >= 8 * OUT) return;
    int b = gw / OUT, o = gw - b * OUT;
    const float* v = vec + b * 512;
    const float* wr = Wm + (size_t)o * 512;
    float s = 0.f;
#pragma unroll 4
    for (int i = lane; i < 512; i += 32) s = fmaf(v[i], wr[i], s);
#pragma unroll
    for (int off = 16; off; off >>= 1) s += __shfl_xor_sync(0xffffffffu, s, off);
    if (lane == 0) out[b * OUT + o] = s + bias[o];
}

// ---------------------------------------------------------------------------
// demod[b,o] = rsqrt( sum_i (sum_k w[o,i,k]^2) * styles[b,i]^2 + eps )
// one block per o, 256 threads, 8 batches accumulated in registers
// ---------------------------------------------------------------------------
__global__ void __launch_bounds__(256) demod_kernel(
    const float* __restrict__ convw, const float* __restrict__ styles,
    float* __restrict__ demod, int CIN, int COUT) {
    int o = blockIdx.x;
    int tid = threadIdx.x;
    float part[8];
#pragma unroll
    for (int b = 0; b < 8; b++) part[b] = 0.f;
    for (int i = tid; i < CIN; i += 256) {
        const float* wp = convw + ((size_t)o * CIN + i) * 9;
        float wsq = 0.f;
#pragma unroll
        for (int k = 0; k < 9; k++) { float t = wp[k]; wsq = fmaf(t, t, wsq); }
#pragma unroll
        for (int b = 0; b < 8; b++) {
            float s = styles[b * CIN + i];
            part[b] = fmaf(wsq, s * s, part[b]);
        }
    }
    __shared__ float sm[8][9];
#pragma unroll
    for (int b = 0; b < 8; b++)
#pragma unroll
        for (int off = 16; off; off >>= 1)
            part[b] += __shfl_xor_sync(0xffffffffu, part[b], off);
    int warp = tid >> 5, lane = tid & 31;
    if (lane == 0)
        for (int b = 0; b < 8; b++) sm[warp][b] = part[b];
    __syncthreads();
    if (tid < 8) {
        float t = 0.f;
        for (int w2 = 0; w2 < 8; w2++) t += sm[w2][tid];
        demod[tid * COUT + o] = rsqrtf(t + DEMOD_EPS);
    }
}

// ---------------------------------------------------------------------------
// Weight transpose: wT[(ci*9+k)*COUT + oc] = w[oc][ci][k]
// ---------------------------------------------------------------------------
__global__ void transpose_w(const float* __restrict__ w, float* __restrict__ wT,
                            int CIN, int COUT) {
    int idx = blockIdx.x * blockDim.x + threadIdx.x;
    int total = CIN * 9 * COUT;
    if (idx >= total) return;
    int oc = idx % COUT;
    int rem = idx / COUT;
    int k = rem % 9;
    int ci = rem / 9;
    wT[idx] = w[((size_t)oc * CIN + ci) * 9 + k];
}

// ---------------------------------------------------------------------------
// Fused modulated 3x3 conv (+ optional on-the-fly bilinear 2x upsample of the
// input) + demod + noise + LeakyReLU(0.1).
// Block tile: 64 output channels x (4 rows x 16 cols) pixels. 256 threads,
// each computes a 4(oc) x 4(pix) register microtile. K chunked by 8 channels.
// ---------------------------------------------------------------------------
template <int CIN, int COUT, int H, int W, bool UP>
__global__ void __launch_bounds__(256) conv3x3_kernel(
    const float* __restrict__ in, const float* __restrict__ wT,
    const float* __restrict__ styles, const float* __restrict__ demod,
    const float* __restrict__ noise, float* __restrict__ out) {
    constexpr int KC = 8;
    constexpr int Hin = UP ? H / 2 : H;
    constexpr int Win = UP ? W / 2 : W;

    __shared__ float s_in[KC][6][21];   // 18 used per row; 21 stride kills conflicts
    __shared__ float s_w[KC][9][64];

    const int tid = threadIdx.x;
    const int x0 = blockIdx.x * 16;
    const int y0 = blockIdx.y * 4;
    const int bz = blockIdx.z;
    const int b = bz / (COUT / 64);
    const int ocb = (bz % (COUT / 64)) * 64;

    const int ty = tid >> 4;         // 0..15 : oc quad
    const int tx = tid & 15;         // 0..15 : pixel quad
    const int r_t = tx >> 2;         // row 0..3
    const int c4 = (tx & 3) * 4;     // col base 0/4/8/12

    float acc[4][4];
#pragma unroll
    for (int i = 0; i < 4; i++)
#pragma unroll
        for (int j = 0; j < 4; j++) acc[i][j] = 0.f;

    for (int c0 = 0; c0 < CIN; c0 += KC) {
        // ---- load input tile (style-scaled, zero-padded, optionally upsampled)
        for (int idx = tid; idx < KC * 6 * 18; idx += 256) {
            int ci = idx / 108;
            int rem = idx - ci * 108;
            int rr = rem / 18;
            int cc = rem - rr * 18;
            int yy = y0 - 1 + rr;
            int xx = x0 - 1 + cc;
            float v = 0.f;
            if (yy >= 0 && yy < H && xx >= 0 && xx < W) {
                const float* plane =
                    in + (size_t)(b * CIN + c0 + ci) * (Hin * Win);
                if (UP) v = bilin_up(plane, yy, xx, Hin, Win);
                else    v = plane[yy * Win + xx];
                v *= styles[b * CIN + c0 + ci];
            }
            s_in[ci][rr][cc] = v;
        }
        // ---- load weight slab (coalesced from pre-transposed layout)
#pragma unroll
        for (int l = 0; l < (KC * 9 * 64) / 256; l++) {
            int idx = tid + l * 256;
            int ci = idx / 576;
            int rem = idx - ci * 576;
            (&s_w[0][0][0])[ci * 576 + rem] =
                wT[(size_t)(c0 + ci) * 9 * COUT + (rem >> 6) * COUT + ocb + (rem & 63)];
        }
        __syncthreads();

#pragma unroll 2
        for (int ci = 0; ci < KC; ci++) {
#pragma unroll
            for (int ky = 0; ky < 3; ky++) {
                float iv[6];
#pragma unroll
                for (int j = 0; j < 6; j++) iv[j] = s_in[ci][r_t + ky][c4 + j];
#pragma unroll
                for (int kx = 0; kx < 3; kx++) {
                    float wv[4];
#pragma unroll
                    for (int oo = 0; oo < 4; oo++)
                        wv[oo] = s_w[ci][ky * 3 + kx][ty * 4 + oo];
#pragma unroll
                    for (int oo = 0; oo < 4; oo++)
#pragma unroll
                        for (int pp = 0; pp < 4; pp++)
                            acc[oo][pp] = fmaf(wv[oo], iv[kx + pp], acc[oo][pp]);
                }
            }
        }
        __syncthreads();
    }

    const int y = y0 + r_t;
#pragma unroll
    for (int oo = 0; oo < 4; oo++) {
        int oc = ocb + ty * 4 + oo;
        float d = demod[b * COUT + oc];
        float nz = noise[b * COUT + oc];
        float* orow = out + ((size_t)(b * COUT + oc) * H + y) * W + x0 + c4;
#pragma unroll
        for (int pp = 0; pp < 4; pp++) {
            float v = fmaf(acc[oo][pp], d, nz);
            orow[pp] = (v >= 0.f) ? v : NEG_SLOPE * v;
        }
    }
}

// ---------------------------------------------------------------------------
// toRGB: rgb_out = (xout . rgb_w + rgb_b + upsample2x(rgb_in)) * sqrt(0.5)
// one thread per (b, y, x); computes all 3 output channels
// ---------------------------------------------------------------------------
__global__ void __launch_bounds__(256) rgb_kernel(
    const float* __restrict__ xout, const float* __restrict__ rgb_in,
    const float* __restrict__ rgb_w, const float* __restrict__ rgb_b,
    float* __restrict__ rgb_out) {
    __shared__ float sw[384];
    for (int i = threadIdx.x; i < 384; i += 256) sw[i] = rgb_w[i];
    __syncthreads();
    int idx = blockIdx.x * 256 + threadIdx.x;
    if (idx >= 8 * 128 * 128) return;
    int b = idx >> 14;
    int p = idx & 16383;
    int y = p >> 7, x = p & 127;
    const float* xp = xout + (size_t)b * 128 * 16384 + p;
    float a0 = 0.f, a1 = 0.f, a2 = 0.f;
#pragma unroll 4
    for (int o = 0; o < 128; o++) {
        float v = xp[(size_t)o * 16384];
        a0 = fmaf(v, sw[o], a0);
        a1 = fmaf(v, sw[128 + o], a1);
        a2 = fmaf(v, sw[256 + o], a2);
    }
    float a[3] = {a0, a1, a2};
#pragma unroll
    for (int c = 0; c < 3; c++) {
        const float* plane = rgb_in + ((size_t)b * 3 + c) * 64 * 64;
        float up = bilin_up(plane, y, x, 64, 64);
        rgb_out[((size_t)(b * 3 + c) * 128 + y) * 128 + x] =
            (a[c] + rgb_b[c] + up) * RES_SCALE;
    }
}

// ---------------------------------------------------------------------------
// Launcher
// ---------------------------------------------------------------------------
extern "C" void kernel_launch(void* const* d_in, const int* in_sizes, int n_in,
                              void* d_out, int out_size) {
    const float* x       = (const float*)d_in[0];   // [8,256,64,64]
    const float* w       = (const float*)d_in[1];   // [8,512]
    const float* n       = (const float*)d_in[2];   // [8,512]
    const float* rgb     = (const float*)d_in[3];   // [8,3,64,64]
    const float* conv1_w = (const float*)d_in[4];   // [256,256,3,3]
    const float* A1_w    = (const float*)d_in[5];   // [256,512]
    const float* A1_b    = (const float*)d_in[6];   // [256]
    const float* B1_w    = (const float*)d_in[7];   // [256,512]
    const float* B1_b    = (const float*)d_in[8];   // [256]
    const float* conv2_w = (const float*)d_in[9];   // [128,256,3,3]
    const float* A2_w    = (const float*)d_in[10];  // [256,512]
    const float* A2_b    = (const float*)d_in[11];  // [256]
    const float* B2_w    = (const float*)d_in[12];  // [128,512]
    const float* B2_b    = (const float*)d_in[13];  // [128]
    const float* rgb_w   = (const float*)d_in[14];  // [3,128,1,1]
    const float* rgb_b   = (const float*)d_in[15];  // [3]

    static float *p_y1 = nullptr, *p_wT1, *p_wT2, *p_s1, *p_n1, *p_s2, *p_n2,
                 *p_d1, *p_d2;
    if (!p_y1) {
        cudaGetSymbolAddress((void**)&p_y1, g_y1);
        cudaGetSymbolAddress((void**)&p_wT1, g_wT1);
        cudaGetSymbolAddress((void**)&p_wT2, g_wT2);
        cudaGetSymbolAddress((void**)&p_s1, g_s1);
        cudaGetSymbolAddress((void**)&p_n1, g_n1);
        cudaGetSymbolAddress((void**)&p_s2, g_s2);
        cudaGetSymbolAddress((void**)&p_n2, g_n2);
        cudaGetSymbolAddress((void**)&p_d1, g_d1);
        cudaGetSymbolAddress((void**)&p_d2, g_d2);
    }

    float* xout = (float*)d_out;                          // [8,128,128,128]
    float* rgbout = xout + (size_t)8 * 128 * 128 * 128;   // [8,3,128,128]

    // styles / noise affines
    affine_kernel<<<256, 256>>>(w, A1_w, A1_b, p_s1, 256);
    affine_kernel<<<256, 256>>>(n, B1_w, B1_b, p_n1, 256);
    affine_kernel<<<256, 256>>>(w, A2_w, A2_b, p_s2, 256);
    affine_kernel<<<128, 256>>>(n, B2_w, B2_b, p_n2, 128);

    // demodulation factors
    demod_kernel<<<256, 256>>>(conv1_w, p_s1, p_d1, 256, 256);
    demod_kernel<<<128, 256>>>(conv2_w, p_s2, p_d2, 256, 128);

    // weight transposes (coalesced conv loads)
    transpose_w<<<(256 * 9 * 256 + 255) / 256, 256>>>(conv1_w, p_wT1, 256, 256);
    transpose_w<<<(256 * 9 * 128 + 255) / 256, 256>>>(conv2_w, p_wT2, 256, 128);

    // block 1: mod-conv 256->256 @64x64 (+demod+noise+lrelu) -> y1
    conv3x3_kernel<256, 256, 64, 64, false>
        <<<dim3(4, 16, 8 * 4), 256>>>(x, p_wT1, p_s1, p_d1, p_n1, p_y1);

    // block 2: upsample(fused) + mod-conv 256->128 @128x128 -> xout
    conv3x3_kernel<256, 128, 128, 128, true>
        <<<dim3(8, 32, 8 * 2), 256>>>(p_y1, p_wT2, p_s2, p_d2, p_n2, xout);

    // toRGB + residual rgb upsample
    rgb_kernel<<<512, 256>>>(xout, rgb, rgb_w, rgb_b, rgbout);
}